// round 5
// baseline (speedup 1.0000x reference)
#include <cuda_runtime.h>
#include <cstdint>

#define NB 16384
#define N1 1024
#define K1 512
#define N2 512
#define K2 1024

// ---------------- device-global scratch (no allocations allowed) ----------
// Fragment-ordered layouts for mma.sync m16n8k8 tf32:
//  A-layout (matrix [M,K] used as mma-A): addr = ((f*(K/8)+s)*32 + t)*4 + j
//  B-layout (matrix [N,K] used as mma-B): addr = ((s*32+t)*(N/8) + g)*2 + j
__device__ float g_zfh[(size_t)NB * K1], g_zfl[(size_t)NB * K1];   // z  frags
__device__ float g_hfh[(size_t)NB * N1], g_hfl[(size_t)NB * N1];   // h  frags
__device__ float g_w1fh[N1 * K1], g_w1fl[N1 * K1];
__device__ float g_w2fh[N2 * K2], g_w2fl[N2 * K2];
__device__ float g_beff1[N1], g_beff2[N2], g_c[N1];
__device__ float g_trp[8][NB];

// ---------------- small helpers -------------------------------------------
__device__ __forceinline__ float tf32_rna(float x) {
    uint32_t u;
    asm("cvt.rna.tf32.f32 %0, %1;" : "=r"(u) : "f"(x));
    return __uint_as_float(u);
}
__device__ __forceinline__ uint32_t smem_u32(const void* p) {
    uint32_t a;
    asm("{ .reg .u64 t; cvta.to.shared.u64 t, %1; cvt.u32.u64 %0, t; }" : "=r"(a) : "l"(p));
    return a;
}
#define CP16(dst, src) \
    asm volatile("cp.async.cg.shared.global [%0], [%1], 16;" \
        :: "r"(dst), "l"(__cvta_generic_to_global(src)))
#define CP_COMMIT() asm volatile("cp.async.commit_group;")
#define CP_WAIT1()  asm volatile("cp.async.wait_group 1;")
#define CP_WAIT0()  asm volatile("cp.async.wait_group 0;")

#define LDS128(r, addr) \
    asm volatile("ld.shared.v4.b32 {%0,%1,%2,%3}, [%4];" \
        : "=r"((r)[0]), "=r"((r)[1]), "=r"((r)[2]), "=r"((r)[3]) : "r"(addr))

__device__ __forceinline__ void mma_tf32(float* d, const uint32_t* a, const uint32_t* b) {
    asm volatile(
        "mma.sync.aligned.m16n8k8.row.col.f32.tf32.tf32.f32 "
        "{%0,%1,%2,%3}, {%4,%5,%6,%7}, {%8,%9}, {%0,%1,%2,%3};"
        : "+f"(d[0]), "+f"(d[1]), "+f"(d[2]), "+f"(d[3])
        : "r"(a[0]), "r"(a[1]), "r"(a[2]), "r"(a[3]), "r"(b[0]), "r"(b[1]));
}

// exact fp64 recompute of h_pre sign for uncertain elements (rare: ~13k of 16.7M)
__device__ __noinline__ bool exact_mask(const float* __restrict__ z,
                                        const float* __restrict__ W1,
                                        int row, int col) {
    const float* zr = z + (size_t)row * K1;
    const float* wr = W1 + (size_t)col * (K1 + 1);
    double s = 0.0;
    #pragma unroll 4
    for (int d = 0; d < K1; d++) s += (double)zr[d] * (double)wr[d];
    s += (double)g_beff1[col];
    return s > 0.0;
}

// ---------------- prep kernels --------------------------------------------
__global__ void prep_w(const float* __restrict__ W1, const float* __restrict__ W2) {
    int idx = blockIdx.x * 256 + threadIdx.x;
    if (idx < N1 * K1) {
        int n = idx >> 9, k = idx & 511;
        float x = W1[n * 513 + k];
        float hi = tf32_rna(x), lo = tf32_rna(x - hi);
        int s = k >> 3, t = ((n & 7) << 2) | (k & 3), g = n >> 3, j = (k >> 2) & 1;
        int off = ((s * 32 + t) * (N1 / 8) + g) * 2 + j;
        g_w1fh[off] = hi; g_w1fl[off] = lo;
    } else {
        int i2 = idx - N1 * K1;
        if (i2 < N2 * K2) {
            int n = i2 >> 10, k = i2 & 1023;
            float x = W2[n * 1025 + k];
            float hi = tf32_rna(x), lo = tf32_rna(x - hi);
            int s = k >> 3, t = ((n & 7) << 2) | (k & 3), g = n >> 3, j = (k >> 2) & 1;
            int off = ((s * 32 + t) * (N2 / 8) + g) * 2 + j;
            g_w2fh[off] = hi; g_w2fl[off] = lo;
        }
    }
}

__global__ void prep_z(const float* __restrict__ z) {
    int i4 = blockIdx.x * 256 + threadIdx.x;         // float4 index, exact grid
    int m = i4 >> 7, q = i4 & 127;                   // k0 = 4q
    float4 v = *((const float4*)z + i4);
    int f = m >> 4, s = q >> 1;
    int j = ((m >> 3) & 1) + ((q & 1) << 1);
    int tb = (m & 7) << 2;
    int base = ((f * (K1 / 8) + s) * 32 + tb) * 4 + j;
    const float* vp = &v.x;
    #pragma unroll
    for (int w = 0; w < 4; w++) {
        float hi = tf32_rna(vp[w]);
        g_zfh[base + 4 * w] = hi;
        g_zfl[base + 4 * w] = tf32_rna(vp[w] - hi);
    }
}

__global__ void prep_cbias(const float* __restrict__ t,
                           const float* __restrict__ W1, const float* __restrict__ b1,
                           const float* __restrict__ W2, const float* __restrict__ b2) {
    int j = blockIdx.x * 256 + threadIdx.x;
    float t0 = t[0];
    if (j < N1) {
        const float* w1row = W1 + (size_t)j * 513;
        float s = 0.f;
        #pragma unroll 4
        for (int k = 0; k < K1; k++)
            s += W2[(size_t)k * 1025 + j] * w1row[k];
        g_c[j] = s;
        g_beff1[j] = b1[j] + t0 * w1row[512];
    }
    if (j < N2) g_beff2[j] = b2[j] + t0 * W2[(size_t)j * 1025 + 1024];
}

__global__ void trace_combine(float* __restrict__ out) {
    int i = blockIdx.x * 256 + threadIdx.x;
    float s = 0.f;
    #pragma unroll
    for (int b = 0; b < 8; b++) s += g_trp[b][i];
    out[(size_t)NB * N2 + i] = -s;
}

// ---------------- 3xTF32 mma.sync GEMM ------------------------------------
// C[M,N] = A@B^T (+bias). Block 128x128x32, 8 warps (2m x 4n), warp 64x32.
// 3-stage cp.async pipeline. PHASE1 -> relu h (frag hi/lo) + trace partials.
// PHASE2 -> dz row-major.
static constexpr int ST_AL = 16384;
static constexpr int ST_BH = 32768;
static constexpr int ST_BL = 51200;
static constexpr int ST_SZ = 69632;
static constexpr int SMEM_BYTES = 3 * ST_SZ;   // 208896
static constexpr float TAU = 1e-3f;            // ~100 sigma of tf32x3 h_pre error

template<int PHASE>
__global__ void __launch_bounds__(256) tc_gemm(float* __restrict__ outp,
                                               const float* __restrict__ zP,
                                               const float* __restrict__ W1P) {
    constexpr int N  = (PHASE == 1) ? N1 : N2;
    constexpr int K  = (PHASE == 1) ? K1 : K2;
    constexpr int KS = K / 8;
    constexpr int NG = N / 8;
    constexpr int NC = K / 32;

    const float* Ah = (PHASE == 1) ? g_zfh  : g_hfh;
    const float* Al = (PHASE == 1) ? g_zfl  : g_hfl;
    const float* Bh = (PHASE == 1) ? g_w1fh : g_w2fh;
    const float* Bl = (PHASE == 1) ? g_w1fl : g_w2fl;
    const float* bias = (PHASE == 1) ? g_beff1 : g_beff2;

    extern __shared__ char smem[];
    const uint32_t sbase = smem_u32(smem);
    const int tid = threadIdx.x, lane = tid & 31, wid = tid >> 5;
    const int wm = wid >> 2, wn = wid & 3;
    const int f0 = blockIdx.y * 8;    // m0/16
    const int g0 = blockIdx.x * 16;   // n0/8

    auto load_stage = [&](int buf, int c) {
        uint32_t st = sbase + buf * ST_SZ;
        int s0 = c * 4;
        #pragma unroll
        for (int i = 0; i < 4; i++) {            // A: 1024 chunks x16B per plane
            int idx = tid + i * 256;
            int s = idx >> 8, f = (idx >> 5) & 7, t = idx & 31;
            size_t go = (((size_t)(f0 + f) * KS + s0 + s) * 32 + t) * 4;
            uint32_t so = (uint32_t)(((s * 8 + f) * 32 + t) * 16);
            CP16(st + so,         Ah + go);
            CP16(st + ST_AL + so, Al + go);
        }
        #pragma unroll
        for (int i = 0; i < 4; i++) {            // B: 1024 chunks x16B per plane
            int idx = tid + i * 256;
            int s = idx >> 8, t = (idx >> 3) & 31, q = idx & 7;
            size_t go = (((size_t)(s0 + s) * 32 + t) * NG + g0 + 2 * q) * 2;
            uint32_t so = (uint32_t)((s * 32 + t) * 144 + 16 * q);
            CP16(st + ST_BH + so, Bh + go);
            CP16(st + ST_BL + so, Bl + go);
        }
    };

    float acc[4][4][4];
    #pragma unroll
    for (int a = 0; a < 4; a++)
        #pragma unroll
        for (int b = 0; b < 4; b++)
            #pragma unroll
            for (int c = 0; c < 4; c++) acc[a][b][c] = 0.f;

    load_stage(0, 0); CP_COMMIT();
    load_stage(1, 1); CP_COMMIT();

    for (int c = 0; c < NC; c++) {
        CP_WAIT1();
        __syncthreads();
        if (c + 2 < NC) load_stage((c + 2) % 3, c + 2);
        CP_COMMIT();

        uint32_t st = sbase + (c % 3) * ST_SZ;
        #pragma unroll
        for (int s = 0; s < 4; s++) {
            uint32_t ah[4][4], al[4][4];
            #pragma unroll
            for (int mi = 0; mi < 4; mi++) {
                uint32_t ao = st + ((s * 8 + wm * 4 + mi) * 32 + lane) * 16;
                LDS128(ah[mi], ao);
                LDS128(al[mi], ao + ST_AL);
            }
            uint32_t bh[8], bl[8];
            #pragma unroll
            for (int p = 0; p < 2; p++) {
                uint32_t bo = st + ST_BH + (s * 32 + lane) * 144 + (wn * 4 + 2 * p) * 8;
                LDS128(&bh[4 * p], bo);
                LDS128(&bl[4 * p], bo + (ST_BL - ST_BH));
            }
            #pragma unroll
            for (int mi = 0; mi < 4; mi++)
                #pragma unroll
                for (int ni = 0; ni < 4; ni++) {
                    mma_tf32(acc[mi][ni], ah[mi], &bh[2 * ni]);
                    mma_tf32(acc[mi][ni], ah[mi], &bl[2 * ni]);
                    mma_tf32(acc[mi][ni], al[mi], &bh[2 * ni]);
                }
        }
    }
    CP_WAIT0();
    __syncthreads();

    // ---------------- epilogue ----------------
    float2 bia[4];
    #pragma unroll
    for (int ni = 0; ni < 4; ni++) {
        int col = blockIdx.x * 128 + wn * 32 + ni * 8 + 2 * (lane & 3);
        bia[ni] = *(const float2*)(bias + col);
    }

    if (PHASE == 1) {
        float2 cc[4];
        #pragma unroll
        for (int ni = 0; ni < 4; ni++) {
            int col = blockIdx.x * 128 + wn * 32 + ni * 8 + 2 * (lane & 3);
            cc[ni] = *(const float2*)(g_c + col);
        }
        float* S = (float*)smem;                   // [n][m], stride 132
        float* TRB = (float*)(smem + 67584);       // [4 wn][128 rows]
        float tr[8] = {0, 0, 0, 0, 0, 0, 0, 0};
        #pragma unroll
        for (int mi = 0; mi < 4; mi++)
            #pragma unroll
            for (int ni = 0; ni < 4; ni++)
                #pragma unroll
                for (int h2 = 0; h2 < 2; h2++) {
                    int mloc = wm * 64 + mi * 16 + (lane >> 2) + 8 * h2;
                    int nb = wn * 32 + ni * 8 + 2 * (lane & 3);
                    float v0 = acc[mi][ni][2 * h2 + 0] + bia[ni].x;
                    float v1 = acc[mi][ni][2 * h2 + 1] + bia[ni].y;
                    // trace mask: trust sign when far from zero; else exact fp64
                    bool msk0 = (fabsf(v0) > TAU)
                        ? (v0 > 0.f)
                        : exact_mask(zP, W1P, blockIdx.y * 128 + mloc,
                                     blockIdx.x * 128 + nb);
                    bool msk1 = (fabsf(v1) > TAU)
                        ? (v1 > 0.f)
                        : exact_mask(zP, W1P, blockIdx.y * 128 + mloc,
                                     blockIdx.x * 128 + nb + 1);
                    if (msk0) tr[mi * 2 + h2] += cc[ni].x;
                    if (msk1) tr[mi * 2 + h2] += cc[ni].y;
                    S[nb * 132 + mloc]       = fmaxf(v0, 0.f);
                    S[(nb + 1) * 132 + mloc] = fmaxf(v1, 0.f);
                }
        #pragma unroll
        for (int r = 0; r < 8; r++) {
            tr[r] += __shfl_xor_sync(0xffffffffu, tr[r], 1);
            tr[r] += __shfl_xor_sync(0xffffffffu, tr[r], 2);
        }
        if ((lane & 3) == 0) {
            #pragma unroll
            for (int r = 0; r < 8; r++) {
                int row = wm * 64 + (r >> 1) * 16 + (r & 1) * 8 + (lane >> 2);
                TRB[wn * 128 + row] = tr[r];
            }
        }
        __syncthreads();

        // frag-order h write (hi/lo planes) for GEMM2 consumption
        #pragma unroll
        for (int i = 0; i < 16; i++) {
            int idx = tid + i * 256;               // (f*16 + s)*32 + t
            int fl = idx >> 9, sl = (idx >> 5) & 15, t = idx & 31;
            float4 hi, lo;
            float* hp = &hi.x;
            float* lp = &lo.x;
            #pragma unroll
            for (int j = 0; j < 4; j++) {
                int m = fl * 16 + (t >> 2) + 8 * (j & 1);
                int n = sl * 8 + (t & 3) + 4 * (j >> 1);
                float v = S[n * 132 + m];
                float h = tf32_rna(v);
                hp[j] = h;
                lp[j] = tf32_rna(v - h);
            }
            size_t go = (((size_t)(f0 + fl) * (K2 / 8) + (g0 + sl)) * 32 + t) * 4;
            *(float4*)(g_hfh + go) = hi;
            *(float4*)(g_hfl + go) = lo;
        }
        if (tid < 128) {
            float s4 = TRB[tid] + TRB[128 + tid] + TRB[256 + tid] + TRB[384 + tid];
            g_trp[blockIdx.x][blockIdx.y * 128 + tid] = s4;
        }
    } else {
        #pragma unroll
        for (int mi = 0; mi < 4; mi++)
            #pragma unroll
            for (int ni = 0; ni < 4; ni++)
                #pragma unroll
                for (int h2 = 0; h2 < 2; h2++) {
                    int m = blockIdx.y * 128 + wm * 64 + mi * 16 + (lane >> 2) + 8 * h2;
                    int n = blockIdx.x * 128 + wn * 32 + ni * 8 + 2 * (lane & 3);
                    float2 o;
                    o.x = acc[mi][ni][2 * h2 + 0] + bia[ni].x;
                    o.y = acc[mi][ni][2 * h2 + 1] + bia[ni].y;
                    *(float2*)(outp + (size_t)m * N2 + n) = o;
                }
    }
}

// ---------------------------------------------------------------------------
extern "C" void kernel_launch(void* const* d_in, const int* in_sizes, int n_in,
                              void* d_out, int out_size) {
    const float* t  = (const float*)d_in[0];
    const float* z  = (const float*)d_in[1];
    const float* W1 = (const float*)d_in[3];
    const float* b1 = (const float*)d_in[4];
    const float* W2 = (const float*)d_in[5];
    const float* b2 = (const float*)d_in[6];
    float* out = (float*)d_out;     // dz (NB*512) then dlogp (NB)

    cudaFuncSetAttribute(tc_gemm<1>, cudaFuncAttributeMaxDynamicSharedMemorySize, SMEM_BYTES);
    cudaFuncSetAttribute(tc_gemm<2>, cudaFuncAttributeMaxDynamicSharedMemorySize, SMEM_BYTES);

    prep_w<<<(N1 * K1 + N2 * K2 + 255) / 256, 256>>>(W1, W2);
    prep_z<<<(NB * K1 / 4) / 256, 256>>>(z);
    prep_cbias<<<4, 256>>>(t, W1, b1, W2, b2);

    { dim3 g(N1 / 128, NB / 128); tc_gemm<1><<<g, 256, SMEM_BYTES>>>(nullptr, z, W1); }
    { dim3 g(N2 / 128, NB / 128); tc_gemm<2><<<g, 256, SMEM_BYTES>>>(out, nullptr, nullptr); }

    trace_combine<<<NB / 256, 256>>>(out);
}

// round 6
// speedup vs baseline: 1.4459x; 1.4459x over previous
#include <cuda_runtime.h>
#include <cuda_bf16.h>
#include <cstdint>

#define NB 16384
#define N1 1024
#define K1 512
#define N2 512
#define K2 1024

// ---------------- device-global scratch (no allocations) ------------------
// bf16x2 fragment-packed planes for mma.sync m16n8k16 (row.col):
//  A word addr: ((f*(K/16)+s)*32 + t)*4 + jr   [f=m/16, s=k/16, t=(m%8)*4+((k&7)>>1),
//                                               jr=((m>>3)&1) | ((k%16>=8)<<1), halves = k even/odd]
//  B word addr: ((s*32+t)*(N/8) + g)*2 + j     [g=n/8, t=(n%8)*4+((k&7)>>1), j=(k%16>=8)]
__device__ uint32_t g_zf1[(size_t)NB * K1 / 2], g_zf2[(size_t)NB * K1 / 2];
__device__ uint32_t g_hf1[(size_t)NB * N1 / 2], g_hf2[(size_t)NB * N1 / 2];
__device__ uint32_t g_w1f1[N1 * K1 / 2], g_w1f2[N1 * K1 / 2];
__device__ uint32_t g_w2f1[N2 * K2 / 2], g_w2f2[N2 * K2 / 2];
__device__ float g_beff1[N1], g_beff2[N2], g_c[N1];
__device__ float g_trp[8][NB];

// ---------------- helpers --------------------------------------------------
__device__ __forceinline__ uint32_t smem_u32(const void* p) {
    uint32_t a;
    asm("{ .reg .u64 t; cvta.to.shared.u64 t, %1; cvt.u32.u64 %0, t; }" : "=r"(a) : "l"(p));
    return a;
}
#define CP16(dst, src) \
    asm volatile("cp.async.cg.shared.global [%0], [%1], 16;" \
        :: "r"(dst), "l"(__cvta_generic_to_global(src)))
#define CP_COMMIT() asm volatile("cp.async.commit_group;")
#define CP_WAIT1()  asm volatile("cp.async.wait_group 1;")
#define CP_WAIT0()  asm volatile("cp.async.wait_group 0;")
#define LDS128(r, addr) \
    asm volatile("ld.shared.v4.b32 {%0,%1,%2,%3}, [%4];" \
        : "=r"((r)[0]), "=r"((r)[1]), "=r"((r)[2]), "=r"((r)[3]) : "r"(addr))

__device__ __forceinline__ void mma_bf16(float* d, const uint32_t* a, const uint32_t* b) {
    asm volatile(
        "mma.sync.aligned.m16n8k16.row.col.f32.bf16.bf16.f32 "
        "{%0,%1,%2,%3}, {%4,%5,%6,%7}, {%8,%9}, {%0,%1,%2,%3};"
        : "+f"(d[0]), "+f"(d[1]), "+f"(d[2]), "+f"(d[3])
        : "r"(a[0]), "r"(a[1]), "r"(a[2]), "r"(a[3]), "r"(b[0]), "r"(b[1]));
}

// split two floats to (hi, lo) bf16x2 words; low 16 bits = first (even-k) element
__device__ __forceinline__ void split2(float v0, float v1, uint32_t& w1, uint32_t& w2) {
    __nv_bfloat16 h0 = __float2bfloat16_rn(v0);
    __nv_bfloat16 h1 = __float2bfloat16_rn(v1);
    float r0 = v0 - __bfloat162float(h0);
    float r1 = v1 - __bfloat162float(h1);
    __nv_bfloat16 l0 = __float2bfloat16_rn(r0);
    __nv_bfloat16 l1 = __float2bfloat16_rn(r1);
    w1 = ((uint32_t)__bfloat16_as_ushort(h1) << 16) | __bfloat16_as_ushort(h0);
    w2 = ((uint32_t)__bfloat16_as_ushort(l1) << 16) | __bfloat16_as_ushort(l0);
}

// exact fp64 h_pre sign for uncertain elements (4 parallel partials)
__device__ __noinline__ bool exact_mask(const float* __restrict__ z,
                                        const float* __restrict__ W1,
                                        int row, int col) {
    const float* zr = z + (size_t)row * K1;
    const float* wr = W1 + (size_t)col * (K1 + 1);
    double s0 = 0, s1 = 0, s2 = 0, s3 = 0;
    for (int d = 0; d < K1; d += 4) {
        s0 += (double)zr[d + 0] * (double)wr[d + 0];
        s1 += (double)zr[d + 1] * (double)wr[d + 1];
        s2 += (double)zr[d + 2] * (double)wr[d + 2];
        s3 += (double)zr[d + 3] * (double)wr[d + 3];
    }
    double s = ((s0 + s1) + (s2 + s3)) + (double)g_beff1[col];
    return s > 0.0;
}

// ---------------- prep kernels --------------------------------------------
__global__ void prep_w(const float* __restrict__ W1, const float* __restrict__ W2) {
    int p = blockIdx.x * 256 + threadIdx.x;
    if (p < N1 * K1 / 2) {
        int n = p >> 8, q = p & 255;                // K1/2 = 256 pairs per row
        uint32_t w1, w2;
        split2(W1[n * 513 + 2 * q], W1[n * 513 + 2 * q + 1], w1, w2);
        int s = q >> 3, t = ((n & 7) << 2) | (q & 3), g = n >> 3, j = (q >> 2) & 1;
        int off = ((s * 32 + t) * (N1 / 8) + g) * 2 + j;
        g_w1f1[off] = w1; g_w1f2[off] = w2;
    } else {
        int p2 = p - N1 * K1 / 2;
        if (p2 < N2 * K2 / 2) {
            int n = p2 >> 9, q = p2 & 511;          // K2/2 = 512 pairs per row
            uint32_t w1, w2;
            split2(W2[n * 1025 + 2 * q], W2[n * 1025 + 2 * q + 1], w1, w2);
            int s = q >> 3, t = ((n & 7) << 2) | (q & 3), g = n >> 3, j = (q >> 2) & 1;
            int off = ((s * 32 + t) * (N2 / 8) + g) * 2 + j;
            g_w2f1[off] = w1; g_w2f2[off] = w2;
        }
    }
}

__global__ void prep_z(const float* __restrict__ z) {
    int i4 = blockIdx.x * 256 + threadIdx.x;        // float4 index
    int m = i4 >> 7, qq = (i4 & 127) * 2;           // pairs qq, qq+1
    float4 v = ((const float4*)z)[i4];
    int f = m >> 4;
    #pragma unroll
    for (int pi = 0; pi < 2; pi++) {
        int q = qq + pi;
        float a0 = pi ? v.z : v.x;
        float a1 = pi ? v.w : v.y;
        uint32_t w1, w2;
        split2(a0, a1, w1, w2);
        int s = q >> 3, t = ((m & 7) << 2) | (q & 3);
        int jr = ((m >> 3) & 1) | (((q >> 2) & 1) << 1);
        int off = ((f * (K1 / 16) + s) * 32 + t) * 4 + jr;
        g_zf1[off] = w1; g_zf2[off] = w2;
    }
}

// tiled c/bias prep: 8 blocks x 128 threads, coalesced W2 tile loads
__global__ void prep_cbias(const float* __restrict__ t,
                           const float* __restrict__ W1, const float* __restrict__ b1,
                           const float* __restrict__ W2, const float* __restrict__ b2) {
    __shared__ float sm[32][129];
    int j = blockIdx.x * 128 + threadIdx.x;
    float t0 = t[0];
    const float* w1row = W1 + (size_t)j * 513;
    float acc = 0.f;
    for (int k0 = 0; k0 < K1; k0 += 32) {
        #pragma unroll
        for (int i = 0; i < 32; i++) {
            int idx = threadIdx.x + i * 128;
            int kk = idx >> 7, jj = idx & 127;
            sm[kk][jj] = W2[(size_t)(k0 + kk) * 1025 + blockIdx.x * 128 + jj];
        }
        __syncthreads();
        #pragma unroll 8
        for (int kk = 0; kk < 32; kk++)
            acc += sm[kk][threadIdx.x] * w1row[k0 + kk];
        __syncthreads();
    }
    g_c[j] = acc;
    g_beff1[j] = b1[j] + t0 * w1row[512];
    if (j < N2) g_beff2[j] = b2[j] + t0 * W2[(size_t)j * 1025 + 1024];
}

__global__ void trace_combine(float* __restrict__ out) {
    int i = blockIdx.x * 256 + threadIdx.x;
    float s = 0.f;
    #pragma unroll
    for (int b = 0; b < 8; b++) s += g_trp[b][i];
    out[(size_t)NB * N2 + i] = -s;
}

// ---------------- bf16x3 mma.sync GEMM ------------------------------------
// Block 128x128x32, 8 warps (2m x 4n), warp 64x32, 3-stage cp.async, 2 CTAs/SM.
static constexpr int ST_A2 = 8192;
static constexpr int ST_B1 = 16384;
static constexpr int ST_B2 = 25600;
static constexpr int ST_SZ = 34816;
static constexpr int SMEM_BYTES = 3 * ST_SZ;   // 104448
static constexpr float TAU = 1e-3f;

template<int PHASE>
__global__ void __launch_bounds__(256, 2) tc_gemm(float* __restrict__ outp,
                                                  const float* __restrict__ zP,
                                                  const float* __restrict__ W1P) {
    constexpr int N   = (PHASE == 1) ? N1 : N2;
    constexpr int K   = (PHASE == 1) ? K1 : K2;
    constexpr int KS16 = K / 16;
    constexpr int NG  = N / 8;
    constexpr int NC  = K / 32;

    const uint32_t* A1 = (PHASE == 1) ? g_zf1  : g_hf1;
    const uint32_t* A2 = (PHASE == 1) ? g_zf2  : g_hf2;
    const uint32_t* B1 = (PHASE == 1) ? g_w1f1 : g_w2f1;
    const uint32_t* B2 = (PHASE == 1) ? g_w1f2 : g_w2f2;
    const float* bias  = (PHASE == 1) ? g_beff1 : g_beff2;

    extern __shared__ char smem[];
    const uint32_t sbase = smem_u32(smem);
    const int tid = threadIdx.x, lane = tid & 31, wid = tid >> 5;
    const int wm = wid >> 2, wn = wid & 3;
    const int f0 = blockIdx.y * 8;     // m0/16
    const int g0 = blockIdx.x * 16;    // n0/8

    auto load_stage = [&](int buf, int c) {
        uint32_t st = sbase + buf * ST_SZ;
        int s0u = c * 2;
        #pragma unroll
        for (int i = 0; i < 2; i++) {              // A: 512 x 16B per plane
            int idx = tid + i * 256;
            int s = idx >> 8, f = (idx >> 5) & 7, tt = idx & 31;
            size_t go = (((size_t)(f0 + f) * KS16 + s0u + s) * 32 + tt) * 4;
            uint32_t so = (uint32_t)(((s * 8 + f) * 32 + tt) * 16);
            CP16(st + so,         A1 + go);
            CP16(st + ST_A2 + so, A2 + go);
        }
        #pragma unroll
        for (int i = 0; i < 2; i++) {              // B: 512 x 16B per plane
            int idx = tid + i * 256;
            int s = idx >> 8, tt = (idx >> 3) & 31, q = idx & 7;
            size_t go = (((size_t)(s0u + s) * 32 + tt) * NG + g0 + 2 * q) * 2;
            uint32_t so = (uint32_t)((s * 32 + tt) * 144 + 16 * q);
            CP16(st + ST_B1 + so, B1 + go);
            CP16(st + ST_B2 + so, B2 + go);
        }
    };

    float acc[4][4][4];
    #pragma unroll
    for (int a = 0; a < 4; a++)
        #pragma unroll
        for (int b = 0; b < 4; b++)
            #pragma unroll
            for (int c = 0; c < 4; c++) acc[a][b][c] = 0.f;

    load_stage(0, 0); CP_COMMIT();
    load_stage(1, 1); CP_COMMIT();

    for (int c = 0; c < NC; c++) {
        CP_WAIT1();
        __syncthreads();
        if (c + 2 < NC) load_stage((c + 2) % 3, c + 2);
        CP_COMMIT();

        uint32_t st = sbase + (c % 3) * ST_SZ;
        #pragma unroll
        for (int s = 0; s < 2; s++) {
            uint32_t a1[4][4], a2[4][4];
            #pragma unroll
            for (int mi = 0; mi < 4; mi++) {
                uint32_t ao = st + ((s * 8 + wm * 4 + mi) * 32 + lane) * 16;
                LDS128(a1[mi], ao);
                LDS128(a2[mi], ao + ST_A2);
            }
            uint32_t b1[8], b2[8];
            #pragma unroll
            for (int p = 0; p < 2; p++) {
                uint32_t bo = st + ST_B1 + (s * 32 + lane) * 144 + (wn * 4 + 2 * p) * 8;
                LDS128(&b1[4 * p], bo);
                LDS128(&b2[4 * p], bo + (ST_B2 - ST_B1));
            }
            // product-separated ordering: breaks same-acc dependency chains
            #pragma unroll
            for (int mi = 0; mi < 4; mi++)
                #pragma unroll
                for (int ni = 0; ni < 4; ni++)
                    mma_bf16(acc[mi][ni], a1[mi], &b1[2 * ni]);
            #pragma unroll
            for (int mi = 0; mi < 4; mi++)
                #pragma unroll
                for (int ni = 0; ni < 4; ni++)
                    mma_bf16(acc[mi][ni], a1[mi], &b2[2 * ni]);
            #pragma unroll
            for (int mi = 0; mi < 4; mi++)
                #pragma unroll
                for (int ni = 0; ni < 4; ni++)
                    mma_bf16(acc[mi][ni], a2[mi], &b1[2 * ni]);
        }
    }
    CP_WAIT0();
    __syncthreads();

    // ---------------- epilogue ----------------
    float2 bia[4];
    #pragma unroll
    for (int ni = 0; ni < 4; ni++) {
        int col = blockIdx.x * 128 + wn * 32 + ni * 8 + 2 * (lane & 3);
        bia[ni] = *(const float2*)(bias + col);
    }

    if (PHASE == 1) {
        float2 cc[4];
        #pragma unroll
        for (int ni = 0; ni < 4; ni++) {
            int col = blockIdx.x * 128 + wn * 32 + ni * 8 + 2 * (lane & 3);
            cc[ni] = *(const float2*)(g_c + col);
        }
        float* S = (float*)smem;                   // [n][m], stride 132
        float* TRB = (float*)(smem + 67584);       // [4 wn][128 rows]
        float tr[8] = {0, 0, 0, 0, 0, 0, 0, 0};
        #pragma unroll
        for (int mi = 0; mi < 4; mi++)
            #pragma unroll
            for (int ni = 0; ni < 4; ni++)
                #pragma unroll
                for (int h2 = 0; h2 < 2; h2++) {
                    int mloc = wm * 64 + mi * 16 + (lane >> 2) + 8 * h2;
                    int nb = wn * 32 + ni * 8 + 2 * (lane & 3);
                    float v0 = acc[mi][ni][2 * h2 + 0] + bia[ni].x;
                    float v1 = acc[mi][ni][2 * h2 + 1] + bia[ni].y;
                    bool msk0 = (fabsf(v0) > TAU)
                        ? (v0 > 0.f)
                        : exact_mask(zP, W1P, blockIdx.y * 128 + mloc,
                                     blockIdx.x * 128 + nb);
                    bool msk1 = (fabsf(v1) > TAU)
                        ? (v1 > 0.f)
                        : exact_mask(zP, W1P, blockIdx.y * 128 + mloc,
                                     blockIdx.x * 128 + nb + 1);
                    if (msk0) tr[mi * 2 + h2] += cc[ni].x;
                    if (msk1) tr[mi * 2 + h2] += cc[ni].y;
                    S[nb * 132 + mloc]       = fmaxf(v0, 0.f);
                    S[(nb + 1) * 132 + mloc] = fmaxf(v1, 0.f);
                }
        #pragma unroll
        for (int r = 0; r < 8; r++) {
            tr[r] += __shfl_xor_sync(0xffffffffu, tr[r], 1);
            tr[r] += __shfl_xor_sync(0xffffffffu, tr[r], 2);
        }
        if ((lane & 3) == 0) {
            #pragma unroll
            for (int r = 0; r < 8; r++) {
                int row = wm * 64 + (r >> 1) * 16 + (r & 1) * 8 + (lane >> 2);
                TRB[wn * 128 + row] = tr[r];
            }
        }
        __syncthreads();

        // write h as bf16 hi/lo fragment planes for GEMM2 (coalesced u32)
        #pragma unroll
        for (int i = 0; i < 32; i++) {
            int idx = tid + i * 256;               // 0..8191 words
            int fl = idx >> 10, sl = (idx >> 7) & 7, tt = (idx >> 2) & 31, jr = idx & 3;
            int mloc = fl * 16 + (tt >> 2) + 8 * (jr & 1);
            int qloc = sl * 8 + (tt & 3) + 4 * (jr >> 1);
            float v0 = S[(2 * qloc) * 132 + mloc];
            float v1 = S[(2 * qloc + 1) * 132 + mloc];
            uint32_t w1, w2;
            split2(v0, v1, w1, w2);
            size_t go = (((size_t)(f0 + fl) * (K2 / 16) + blockIdx.x * 8 + sl) * 32 + tt) * 4 + jr;
            g_hf1[go] = w1;
            g_hf2[go] = w2;
        }
        if (tid < 128) {
            float s4 = TRB[tid] + TRB[128 + tid] + TRB[256 + tid] + TRB[384 + tid];
            g_trp[blockIdx.x][blockIdx.y * 128 + tid] = s4;
        }
    } else {
        #pragma unroll
        for (int mi = 0; mi < 4; mi++)
            #pragma unroll
            for (int ni = 0; ni < 4; ni++)
                #pragma unroll
                for (int h2 = 0; h2 < 2; h2++) {
                    int m = blockIdx.y * 128 + wm * 64 + mi * 16 + (lane >> 2) + 8 * h2;
                    int n = blockIdx.x * 128 + wn * 32 + ni * 8 + 2 * (lane & 3);
                    float2 o;
                    o.x = acc[mi][ni][2 * h2 + 0] + bia[ni].x;
                    o.y = acc[mi][ni][2 * h2 + 1] + bia[ni].y;
                    *(float2*)(outp + (size_t)m * N2 + n) = o;
                }
    }
}

// ---------------------------------------------------------------------------
extern "C" void kernel_launch(void* const* d_in, const int* in_sizes, int n_in,
                              void* d_out, int out_size) {
    const float* t  = (const float*)d_in[0];
    const float* z  = (const float*)d_in[1];
    const float* W1 = (const float*)d_in[3];
    const float* b1 = (const float*)d_in[4];
    const float* W2 = (const float*)d_in[5];
    const float* b2 = (const float*)d_in[6];
    float* out = (float*)d_out;     // dz (NB*512) then dlogp (NB)

    cudaFuncSetAttribute(tc_gemm<1>, cudaFuncAttributeMaxDynamicSharedMemorySize, SMEM_BYTES);
    cudaFuncSetAttribute(tc_gemm<2>, cudaFuncAttributeMaxDynamicSharedMemorySize, SMEM_BYTES);

    prep_w<<<(N1 * K1 / 2 + N2 * K2 / 2 + 255) / 256, 256>>>(W1, W2);
    prep_z<<<(NB * K1 / 4) / 256, 256>>>(z);
    prep_cbias<<<8, 128>>>(t, W1, b1, W2, b2);

    { dim3 g(N1 / 128, NB / 128); tc_gemm<1><<<g, 256, SMEM_BYTES>>>(nullptr, z, W1); }
    { dim3 g(N2 / 128, NB / 128); tc_gemm<2><<<g, 256, SMEM_BYTES>>>(out, nullptr, nullptr); }

    trace_combine<<<NB / 256, 256>>>(out);
}

// round 7
// speedup vs baseline: 1.4625x; 1.0115x over previous
#include <cuda_runtime.h>
#include <cuda_bf16.h>
#include <cstdint>

#define NB 16384
#define N1 1024
#define K1 512
#define N2 512
#define K2 1024

// ---------------- device-global scratch (no allocations) ------------------
// bf16x2 fragment-packed planes for mma.sync m16n8k16 (row.col):
//  A word addr: ((f*(K/16)+s)*32 + t)*4 + jr   [f=m/16, s=k/16, t=(m%8)*4+((k&7)>>1),
//                                               jr=((m>>3)&1) | ((k%16>=8)<<1), halves = k even/odd]
//  B word addr: ((s*32+t)*(N/8) + g)*2 + j     [g=n/8, t=(n%8)*4+((k&7)>>1), j=(k%16>=8)]
__device__ uint32_t g_zf1[(size_t)NB * K1 / 2], g_zf2[(size_t)NB * K1 / 2];
__device__ uint32_t g_hf1[(size_t)NB * N1 / 2], g_hf2[(size_t)NB * N1 / 2];
__device__ uint32_t g_w1f1[N1 * K1 / 2], g_w1f2[N1 * K1 / 2];
__device__ uint32_t g_w2f1[N2 * K2 / 2], g_w2f2[N2 * K2 / 2];
__device__ float g_beff1[N1], g_beff2[N2], g_c[N1];
__device__ float g_trp[8][NB];

// ---------------- helpers --------------------------------------------------
__device__ __forceinline__ uint32_t smem_u32(const void* p) {
    uint32_t a;
    asm("{ .reg .u64 t; cvta.to.shared.u64 t, %1; cvt.u32.u64 %0, t; }" : "=r"(a) : "l"(p));
    return a;
}
#define CP16(dst, src) \
    asm volatile("cp.async.cg.shared.global [%0], [%1], 16;" \
        :: "r"(dst), "l"(__cvta_generic_to_global(src)))
#define CP_COMMIT() asm volatile("cp.async.commit_group;")
#define CP_WAIT1()  asm volatile("cp.async.wait_group 1;")
#define CP_WAIT0()  asm volatile("cp.async.wait_group 0;")
#define LDS128(r, addr) \
    asm volatile("ld.shared.v4.b32 {%0,%1,%2,%3}, [%4];" \
        : "=r"((r)[0]), "=r"((r)[1]), "=r"((r)[2]), "=r"((r)[3]) : "r"(addr))

__device__ __forceinline__ void mma_bf16(float* d, const uint32_t* a, const uint32_t* b) {
    asm volatile(
        "mma.sync.aligned.m16n8k16.row.col.f32.bf16.bf16.f32 "
        "{%0,%1,%2,%3}, {%4,%5,%6,%7}, {%8,%9}, {%0,%1,%2,%3};"
        : "+f"(d[0]), "+f"(d[1]), "+f"(d[2]), "+f"(d[3])
        : "r"(a[0]), "r"(a[1]), "r"(a[2]), "r"(a[3]), "r"(b[0]), "r"(b[1]));
}

// split two floats to (hi, lo) bf16x2 words; low 16 bits = first (even-k) element
__device__ __forceinline__ void split2(float v0, float v1, uint32_t& w1, uint32_t& w2) {
    __nv_bfloat16 h0 = __float2bfloat16_rn(v0);
    __nv_bfloat16 h1 = __float2bfloat16_rn(v1);
    float r0 = v0 - __bfloat162float(h0);
    float r1 = v1 - __bfloat162float(h1);
    __nv_bfloat16 l0 = __float2bfloat16_rn(r0);
    __nv_bfloat16 l1 = __float2bfloat16_rn(r1);
    w1 = ((uint32_t)__bfloat16_as_ushort(h1) << 16) | __bfloat16_as_ushort(h0);
    w2 = ((uint32_t)__bfloat16_as_ushort(l1) << 16) | __bfloat16_as_ushort(l0);
}

// exact fp64 h_pre sign for uncertain elements (4 parallel partials)
__device__ __noinline__ bool exact_mask(const float* __restrict__ z,
                                        const float* __restrict__ W1,
                                        int row, int col) {
    const float* zr = z + (size_t)row * K1;
    const float* wr = W1 + (size_t)col * (K1 + 1);
    double s0 = 0, s1 = 0, s2 = 0, s3 = 0;
    for (int d = 0; d < K1; d += 4) {
        s0 += (double)zr[d + 0] * (double)wr[d + 0];
        s1 += (double)zr[d + 1] * (double)wr[d + 1];
        s2 += (double)zr[d + 2] * (double)wr[d + 2];
        s3 += (double)zr[d + 3] * (double)wr[d + 3];
    }
    double s = ((s0 + s1) + (s2 + s3)) + (double)g_beff1[col];
    return s > 0.0;
}

// ---------------- prep kernels --------------------------------------------
__global__ void prep_w(const float* __restrict__ W1, const float* __restrict__ W2) {
    int p = blockIdx.x * 256 + threadIdx.x;
    if (p < N1 * K1 / 2) {
        int n = p >> 8, q = p & 255;                // K1/2 = 256 pairs per row
        uint32_t w1, w2;
        split2(W1[n * 513 + 2 * q], W1[n * 513 + 2 * q + 1], w1, w2);
        int s = q >> 3, t = ((n & 7) << 2) | (q & 3), g = n >> 3, j = (q >> 2) & 1;
        int off = ((s * 32 + t) * (N1 / 8) + g) * 2 + j;
        g_w1f1[off] = w1; g_w1f2[off] = w2;
    } else {
        int p2 = p - N1 * K1 / 2;
        if (p2 < N2 * K2 / 2) {
            int n = p2 >> 9, q = p2 & 511;          // K2/2 = 512 pairs per row
            uint32_t w1, w2;
            split2(W2[n * 1025 + 2 * q], W2[n * 1025 + 2 * q + 1], w1, w2);
            int s = q >> 3, t = ((n & 7) << 2) | (q & 3), g = n >> 3, j = (q >> 2) & 1;
            int off = ((s * 32 + t) * (N2 / 8) + g) * 2 + j;
            g_w2f1[off] = w1; g_w2f2[off] = w2;
        }
    }
}

__global__ void prep_z(const float* __restrict__ z) {
    int i4 = blockIdx.x * 256 + threadIdx.x;        // float4 index
    int m = i4 >> 7, qq = (i4 & 127) * 2;           // pairs qq, qq+1
    float4 v = ((const float4*)z)[i4];
    int f = m >> 4;
    #pragma unroll
    for (int pi = 0; pi < 2; pi++) {
        int q = qq + pi;
        float a0 = pi ? v.z : v.x;
        float a1 = pi ? v.w : v.y;
        uint32_t w1, w2;
        split2(a0, a1, w1, w2);
        int s = q >> 3, t = ((m & 7) << 2) | (q & 3);
        int jr = ((m >> 3) & 1) | (((q >> 2) & 1) << 1);
        int off = ((f * (K1 / 16) + s) * 32 + t) * 4 + jr;
        g_zf1[off] = w1; g_zf2[off] = w2;
    }
}

// tiled c/bias prep: 8 blocks x 128 threads, coalesced W2 tile loads
__global__ void prep_cbias(const float* __restrict__ t,
                           const float* __restrict__ W1, const float* __restrict__ b1,
                           const float* __restrict__ W2, const float* __restrict__ b2) {
    __shared__ float sm[32][129];
    int j = blockIdx.x * 128 + threadIdx.x;
    float t0 = t[0];
    const float* w1row = W1 + (size_t)j * 513;
    float acc = 0.f;
    for (int k0 = 0; k0 < K1; k0 += 32) {
        #pragma unroll
        for (int i = 0; i < 32; i++) {
            int idx = threadIdx.x + i * 128;
            int kk = idx >> 7, jj = idx & 127;
            sm[kk][jj] = W2[(size_t)(k0 + kk) * 1025 + blockIdx.x * 128 + jj];
        }
        __syncthreads();
        #pragma unroll 8
        for (int kk = 0; kk < 32; kk++)
            acc += sm[kk][threadIdx.x] * w1row[k0 + kk];
        __syncthreads();
    }
    g_c[j] = acc;
    g_beff1[j] = b1[j] + t0 * w1row[512];
    if (j < N2) g_beff2[j] = b2[j] + t0 * W2[(size_t)j * 1025 + 1024];
}

__global__ void trace_combine(float* __restrict__ out) {
    int i = blockIdx.x * 256 + threadIdx.x;
    float s = 0.f;
    #pragma unroll
    for (int b = 0; b < 8; b++) s += g_trp[b][i];
    out[(size_t)NB * N2 + i] = -s;
}

// ---------------- bf16x3 mma.sync GEMM ------------------------------------
// Block 128x128x32, 8 warps (2m x 4n), warp 64x32, 3-stage cp.async, 2 CTAs/SM.
static constexpr int ST_A2 = 8192;
static constexpr int ST_B1 = 16384;
static constexpr int ST_B2 = 25600;
static constexpr int ST_SZ = 34816;
static constexpr int SMEM_BYTES = 3 * ST_SZ;   // 104448
static constexpr float TAU = 1e-3f;

template<int PHASE>
__global__ void __launch_bounds__(256, 2) tc_gemm(float* __restrict__ outp,
                                                  const float* __restrict__ zP,
                                                  const float* __restrict__ W1P) {
    constexpr int N   = (PHASE == 1) ? N1 : N2;
    constexpr int K   = (PHASE == 1) ? K1 : K2;
    constexpr int KS16 = K / 16;
    constexpr int NG  = N / 8;
    constexpr int NC  = K / 32;

    const uint32_t* A1 = (PHASE == 1) ? g_zf1  : g_hf1;
    const uint32_t* A2 = (PHASE == 1) ? g_zf2  : g_hf2;
    const uint32_t* B1 = (PHASE == 1) ? g_w1f1 : g_w2f1;
    const uint32_t* B2 = (PHASE == 1) ? g_w1f2 : g_w2f2;
    const float* bias  = (PHASE == 1) ? g_beff1 : g_beff2;

    extern __shared__ char smem[];
    const uint32_t sbase = smem_u32(smem);
    const int tid = threadIdx.x, lane = tid & 31, wid = tid >> 5;
    const int wm = wid >> 2, wn = wid & 3;
    const int f0 = blockIdx.y * 8;     // m0/16
    const int g0 = blockIdx.x * 16;    // n0/8

    auto load_stage = [&](int buf, int c) {
        uint32_t st = sbase + buf * ST_SZ;
        int s0u = c * 2;
        #pragma unroll
        for (int i = 0; i < 2; i++) {              // A: 512 x 16B per plane
            int idx = tid + i * 256;
            int s = idx >> 8, f = (idx >> 5) & 7, tt = idx & 31;
            size_t go = (((size_t)(f0 + f) * KS16 + s0u + s) * 32 + tt) * 4;
            uint32_t so = (uint32_t)(((s * 8 + f) * 32 + tt) * 16);
            CP16(st + so,         A1 + go);
            CP16(st + ST_A2 + so, A2 + go);
        }
        #pragma unroll
        for (int i = 0; i < 2; i++) {              // B: 512 x 16B per plane
            int idx = tid + i * 256;
            int s = idx >> 8, tt = (idx >> 3) & 31, q = idx & 7;
            size_t go = (((size_t)(s0u + s) * 32 + tt) * NG + g0 + 2 * q) * 2;
            uint32_t so = (uint32_t)((s * 32 + tt) * 144 + 16 * q);
            CP16(st + ST_B1 + so, B1 + go);
            CP16(st + ST_B2 + so, B2 + go);
        }
    };

    float acc[4][4][4];
    #pragma unroll
    for (int a = 0; a < 4; a++)
        #pragma unroll
        for (int b = 0; b < 4; b++)
            #pragma unroll
            for (int c = 0; c < 4; c++) acc[a][b][c] = 0.f;

    load_stage(0, 0); CP_COMMIT();
    load_stage(1, 1); CP_COMMIT();

    for (int c = 0; c < NC; c++) {
        CP_WAIT1();
        __syncthreads();
        if (c + 2 < NC) load_stage((c + 2) % 3, c + 2);
        CP_COMMIT();

        uint32_t st = sbase + (c % 3) * ST_SZ;
        #pragma unroll
        for (int s = 0; s < 2; s++) {
            uint32_t a1[4][4], a2[4][4];
            #pragma unroll
            for (int mi = 0; mi < 4; mi++) {
                uint32_t ao = st + ((s * 8 + wm * 4 + mi) * 32 + lane) * 16;
                LDS128(a1[mi], ao);
                LDS128(a2[mi], ao + ST_A2);
            }
            uint32_t b1[8], b2[8];
            #pragma unroll
            for (int p = 0; p < 2; p++) {
                uint32_t bo = st + ST_B1 + (s * 32 + lane) * 144 + (wn * 4 + 2 * p) * 8;
                LDS128(&b1[4 * p], bo);
                LDS128(&b2[4 * p], bo + (ST_B2 - ST_B1));
            }
            // product-separated ordering: breaks same-acc dependency chains
            #pragma unroll
            for (int mi = 0; mi < 4; mi++)
                #pragma unroll
                for (int ni = 0; ni < 4; ni++)
                    mma_bf16(acc[mi][ni], a1[mi], &b1[2 * ni]);
            #pragma unroll
            for (int mi = 0; mi < 4; mi++)
                #pragma unroll
                for (int ni = 0; ni < 4; ni++)
                    mma_bf16(acc[mi][ni], a1[mi], &b2[2 * ni]);
            #pragma unroll
            for (int mi = 0; mi < 4; mi++)
                #pragma unroll
                for (int ni = 0; ni < 4; ni++)
                    mma_bf16(acc[mi][ni], a2[mi], &b1[2 * ni]);
        }
    }
    CP_WAIT0();
    __syncthreads();

    // ---------------- epilogue ----------------
    float2 bia[4];
    #pragma unroll
    for (int ni = 0; ni < 4; ni++) {
        int col = blockIdx.x * 128 + wn * 32 + ni * 8 + 2 * (lane & 3);
        bia[ni] = *(const float2*)(bias + col);
    }

    if (PHASE == 1) {
        float2 cc[4];
        #pragma unroll
        for (int ni = 0; ni < 4; ni++) {
            int col = blockIdx.x * 128 + wn * 32 + ni * 8 + 2 * (lane & 3);
            cc[ni] = *(const float2*)(g_c + col);
        }
        float* S = (float*)smem;                   // [n][m], stride 132
        float* TRB = (float*)(smem + 67584);       // [4 wn][128 rows]
        float tr[8] = {0, 0, 0, 0, 0, 0, 0, 0};
        #pragma unroll
        for (int mi = 0; mi < 4; mi++)
            #pragma unroll
            for (int ni = 0; ni < 4; ni++)
                #pragma unroll
                for (int h2 = 0; h2 < 2; h2++) {
                    int mloc = wm * 64 + mi * 16 + (lane >> 2) + 8 * h2;
                    int nb = wn * 32 + ni * 8 + 2 * (lane & 3);
                    float v0 = acc[mi][ni][2 * h2 + 0] + bia[ni].x;
                    float v1 = acc[mi][ni][2 * h2 + 1] + bia[ni].y;
                    bool msk0 = (fabsf(v0) > TAU)
                        ? (v0 > 0.f)
                        : exact_mask(zP, W1P, blockIdx.y * 128 + mloc,
                                     blockIdx.x * 128 + nb);
                    bool msk1 = (fabsf(v1) > TAU)
                        ? (v1 > 0.f)
                        : exact_mask(zP, W1P, blockIdx.y * 128 + mloc,
                                     blockIdx.x * 128 + nb + 1);
                    if (msk0) tr[mi * 2 + h2] += cc[ni].x;
                    if (msk1) tr[mi * 2 + h2] += cc[ni].y;
                    S[nb * 132 + mloc]       = fmaxf(v0, 0.f);
                    S[(nb + 1) * 132 + mloc] = fmaxf(v1, 0.f);
                }
        #pragma unroll
        for (int r = 0; r < 8; r++) {
            tr[r] += __shfl_xor_sync(0xffffffffu, tr[r], 1);
            tr[r] += __shfl_xor_sync(0xffffffffu, tr[r], 2);
        }
        if ((lane & 3) == 0) {
            #pragma unroll
            for (int r = 0; r < 8; r++) {
                int row = wm * 64 + (r >> 1) * 16 + (r & 1) * 8 + (lane >> 2);
                TRB[wn * 128 + row] = tr[r];
            }
        }
        __syncthreads();

        // write h as bf16 hi/lo fragment planes for GEMM2 (coalesced u32)
        #pragma unroll
        for (int i = 0; i < 32; i++) {
            int idx = tid + i * 256;               // 0..8191 words
            int fl = idx >> 10, sl = (idx >> 7) & 7, tt = (idx >> 2) & 31, jr = idx & 3;
            int mloc = fl * 16 + (tt >> 2) + 8 * (jr & 1);
            int qloc = sl * 8 + (tt & 3) + 4 * (jr >> 1);
            float v0 = S[(2 * qloc) * 132 + mloc];
            float v1 = S[(2 * qloc + 1) * 132 + mloc];
            uint32_t w1, w2;
            split2(v0, v1, w1, w2);
            size_t go = (((size_t)(f0 + fl) * (K2 / 16) + blockIdx.x * 8 + sl) * 32 + tt) * 4 + jr;
            g_hf1[go] = w1;
            g_hf2[go] = w2;
        }
        if (tid < 128) {
            float s4 = TRB[tid] + TRB[128 + tid] + TRB[256 + tid] + TRB[384 + tid];
            g_trp[blockIdx.x][blockIdx.y * 128 + tid] = s4;
        }
    } else {
        #pragma unroll
        for (int mi = 0; mi < 4; mi++)
            #pragma unroll
            for (int ni = 0; ni < 4; ni++)
                #pragma unroll
                for (int h2 = 0; h2 < 2; h2++) {
                    int m = blockIdx.y * 128 + wm * 64 + mi * 16 + (lane >> 2) + 8 * h2;
                    int n = blockIdx.x * 128 + wn * 32 + ni * 8 + 2 * (lane & 3);
                    float2 o;
                    o.x = acc[mi][ni][2 * h2 + 0] + bia[ni].x;
                    o.y = acc[mi][ni][2 * h2 + 1] + bia[ni].y;
                    *(float2*)(outp + (size_t)m * N2 + n) = o;
                }
    }
}

// ---------------------------------------------------------------------------
extern "C" void kernel_launch(void* const* d_in, const int* in_sizes, int n_in,
                              void* d_out, int out_size) {
    const float* t  = (const float*)d_in[0];
    const float* z  = (const float*)d_in[1];
    const float* W1 = (const float*)d_in[3];
    const float* b1 = (const float*)d_in[4];
    const float* W2 = (const float*)d_in[5];
    const float* b2 = (const float*)d_in[6];
    float* out = (float*)d_out;     // dz (NB*512) then dlogp (NB)

    cudaFuncSetAttribute(tc_gemm<1>, cudaFuncAttributeMaxDynamicSharedMemorySize, SMEM_BYTES);
    cudaFuncSetAttribute(tc_gemm<2>, cudaFuncAttributeMaxDynamicSharedMemorySize, SMEM_BYTES);

    prep_w<<<(N1 * K1 / 2 + N2 * K2 / 2 + 255) / 256, 256>>>(W1, W2);
    prep_z<<<(NB * K1 / 4) / 256, 256>>>(z);
    prep_cbias<<<8, 128>>>(t, W1, b1, W2, b2);

    { dim3 g(N1 / 128, NB / 128); tc_gemm<1><<<g, 256, SMEM_BYTES>>>(nullptr, z, W1); }
    { dim3 g(N2 / 128, NB / 128); tc_gemm<2><<<g, 256, SMEM_BYTES>>>(out, nullptr, nullptr); }

    trace_combine<<<NB / 256, 256>>>(out);
}

// round 8
// speedup vs baseline: 1.9682x; 1.3457x over previous
#include <cuda_runtime.h>
#include <cuda_bf16.h>
#include <cstdint>

#define NB 16384
#define N1 1024
#define K1 512
#define N2 512
#define K2 1024
// row partition: ffma rows [0, MF), mma rows [MF, NB)
#define MF 11264          // 88 tiles of 128
#define MR 5120           // 80 tiles of 64
#define F0MG 704          // MF/16

// ---------------- device-global scratch ------------------------------------
__device__ float    g_W1p[N1 * K1], g_W2p[N2 * K2];
__device__ float    g_h[(size_t)MF * N1];
__device__ uint32_t g_zf1[(size_t)NB * K1 / 2], g_zf2[(size_t)NB * K1 / 2];
__device__ uint32_t g_hf1[(size_t)NB * N1 / 2], g_hf2[(size_t)NB * N1 / 2];
__device__ uint32_t g_w1f1[N1 * K1 / 2], g_w1f2[N1 * K1 / 2];
__device__ uint32_t g_w2f1[N2 * K2 / 2], g_w2f2[N2 * K2 / 2];
__device__ float g_beff1[N1], g_beff2[N2], g_c[N1];
__device__ float g_trp[8][NB];

// ---------------- helpers --------------------------------------------------
__device__ __forceinline__ uint32_t smem_u32(const void* p) {
    uint32_t a;
    asm("{ .reg .u64 t; cvta.to.shared.u64 t, %1; cvt.u32.u64 %0, t; }" : "=r"(a) : "l"(p));
    return a;
}
#define CP16(dst, src) \
    asm volatile("cp.async.cg.shared.global [%0], [%1], 16;" \
        :: "r"(dst), "l"(__cvta_generic_to_global(src)))
#define CP_COMMIT() asm volatile("cp.async.commit_group;")
#define CP_WAIT1()  asm volatile("cp.async.wait_group 1;")
#define CP_WAIT0()  asm volatile("cp.async.wait_group 0;")
#define LDS128(r, addr) \
    asm volatile("ld.shared.v4.b32 {%0,%1,%2,%3}, [%4];" \
        : "=r"((r)[0]), "=r"((r)[1]), "=r"((r)[2]), "=r"((r)[3]) : "r"(addr))
#define BARF() asm volatile("bar.sync 1, 256;" ::: "memory")
#define BARM() asm volatile("bar.sync 2, 256;" ::: "memory")

__device__ __forceinline__ void mma_bf16(float* d, const uint32_t* a, const uint32_t* b) {
    asm volatile(
        "mma.sync.aligned.m16n8k16.row.col.f32.bf16.bf16.f32 "
        "{%0,%1,%2,%3}, {%4,%5,%6,%7}, {%8,%9}, {%0,%1,%2,%3};"
        : "+f"(d[0]), "+f"(d[1]), "+f"(d[2]), "+f"(d[3])
        : "r"(a[0]), "r"(a[1]), "r"(a[2]), "r"(a[3]), "r"(b[0]), "r"(b[1]));
}

__device__ __forceinline__ void split2(float v0, float v1, uint32_t& w1, uint32_t& w2) {
    __nv_bfloat16 h0 = __float2bfloat16_rn(v0);
    __nv_bfloat16 h1 = __float2bfloat16_rn(v1);
    float r0 = v0 - __bfloat162float(h0);
    float r1 = v1 - __bfloat162float(h1);
    __nv_bfloat16 l0 = __float2bfloat16_rn(r0);
    __nv_bfloat16 l1 = __float2bfloat16_rn(r1);
    w1 = ((uint32_t)__bfloat16_as_ushort(h1) << 16) | __bfloat16_as_ushort(h0);
    w2 = ((uint32_t)__bfloat16_as_ushort(l1) << 16) | __bfloat16_as_ushort(l0);
}

__device__ __noinline__ bool exact_mask(const float* __restrict__ z,
                                        const float* __restrict__ W1,
                                        int row, int col) {
    const float* zr = z + (size_t)row * K1;
    const float* wr = W1 + (size_t)col * (K1 + 1);
    double s0 = 0, s1 = 0, s2 = 0, s3 = 0;
    for (int d = 0; d < K1; d += 4) {
        s0 += (double)zr[d + 0] * (double)wr[d + 0];
        s1 += (double)zr[d + 1] * (double)wr[d + 1];
        s2 += (double)zr[d + 2] * (double)wr[d + 2];
        s3 += (double)zr[d + 3] * (double)wr[d + 3];
    }
    double s = ((s0 + s1) + (s2 + s3)) + (double)g_beff1[col];
    return s > 0.0;
}

// ---------------- prep kernels ---------------------------------------------
__global__ void prep_pack(const float* __restrict__ W1, const float* __restrict__ W2) {
    int idx = blockIdx.x * 256 + threadIdx.x;
    if (idx < N1 * K1) {
        int n = idx >> 9, k = idx & 511;
        g_W1p[idx] = W1[n * 513 + k];
    } else {
        int j = idx - N1 * K1;
        if (j < N2 * K2) {
            int n = j >> 10, k = j & 1023;
            g_W2p[j] = W2[n * 1025 + k];
        }
    }
}

__global__ void prep_w(const float* __restrict__ W1, const float* __restrict__ W2) {
    int p = blockIdx.x * 256 + threadIdx.x;
    if (p < N1 * K1 / 2) {
        int n = p >> 8, q = p & 255;
        uint32_t w1, w2;
        split2(W1[n * 513 + 2 * q], W1[n * 513 + 2 * q + 1], w1, w2);
        int s = q >> 3, t = ((n & 7) << 2) | (q & 3), g = n >> 3, j = (q >> 2) & 1;
        int off = ((s * 32 + t) * (N1 / 8) + g) * 2 + j;
        g_w1f1[off] = w1; g_w1f2[off] = w2;
    } else {
        int p2 = p - N1 * K1 / 2;
        if (p2 < N2 * K2 / 2) {
            int n = p2 >> 9, q = p2 & 511;
            uint32_t w1, w2;
            split2(W2[n * 1025 + 2 * q], W2[n * 1025 + 2 * q + 1], w1, w2);
            int s = q >> 3, t = ((n & 7) << 2) | (q & 3), g = n >> 3, j = (q >> 2) & 1;
            int off = ((s * 32 + t) * (N2 / 8) + g) * 2 + j;
            g_w2f1[off] = w1; g_w2f2[off] = w2;
        }
    }
}

__global__ void prep_zf(const float* __restrict__ z) {   // mma rows only
    int i4 = MF * (K1 / 4) + blockIdx.x * 256 + threadIdx.x;
    int m = i4 >> 7, qq = (i4 & 127) * 2;
    float4 v = ((const float4*)z)[i4];
    int f = m >> 4;
    #pragma unroll
    for (int pi = 0; pi < 2; pi++) {
        int q = qq + pi;
        float a0 = pi ? v.z : v.x;
        float a1 = pi ? v.w : v.y;
        uint32_t w1, w2;
        split2(a0, a1, w1, w2);
        int s = q >> 3, t = ((m & 7) << 2) | (q & 3);
        int jr = ((m >> 3) & 1) | (((q >> 2) & 1) << 1);
        int off = ((f * (K1 / 16) + s) * 32 + t) * 4 + jr;
        g_zf1[off] = w1; g_zf2[off] = w2;
    }
}

__global__ void prep_cbias(const float* __restrict__ t,
                           const float* __restrict__ W1, const float* __restrict__ b1,
                           const float* __restrict__ W2, const float* __restrict__ b2) {
    __shared__ float sm[32][129];
    int j = blockIdx.x * 128 + threadIdx.x;
    float t0 = t[0];
    const float* w1row = W1 + (size_t)j * 513;
    float acc = 0.f;
    for (int k0 = 0; k0 < K1; k0 += 32) {
        #pragma unroll
        for (int i = 0; i < 32; i++) {
            int idx = threadIdx.x + i * 128;
            int kk = idx >> 7, jj = idx & 127;
            sm[kk][jj] = W2[(size_t)(k0 + kk) * 1025 + blockIdx.x * 128 + jj];
        }
        __syncthreads();
        #pragma unroll 8
        for (int kk = 0; kk < 32; kk++)
            acc += sm[kk][threadIdx.x] * w1row[k0 + kk];
        __syncthreads();
    }
    g_c[j] = acc;
    g_beff1[j] = b1[j] + t0 * w1row[512];
    if (j < N2) g_beff2[j] = b2[j] + t0 * W2[(size_t)j * 1025 + 1024];
}

__global__ void trace_combine(float* __restrict__ out) {   // mma rows only
    int i = MF + blockIdx.x * 256 + threadIdx.x;
    float s = 0.f;
    #pragma unroll
    for (int b = 0; b < 8; b++) s += g_trp[b][i];
    out[(size_t)NB * N2 + i] = -s;
}

// ---------------- smem layout ----------------------------------------------
static constexpr int ST_A2 = 4096;
static constexpr int ST_B1 = 8192;
static constexpr int ST_B2 = 17408;
static constexpr int ST_SZ = 26624;
static constexpr int MM_OFF = 8192;                   // mma region after ffma As/Bs
static constexpr int SMEM_BYTES = MM_OFF + 3 * ST_SZ; // 88064
static constexpr float TAU = 1e-3f;

// ---------------- ffma role (warps 0-7) ------------------------------------
template<int PHASE>
__device__ __forceinline__ void ffma_role(char* smem, float* outX,
                                          const float* __restrict__ zin, int tid) {
    constexpr int K   = (PHASE == 1) ? K1 : K2;
    constexpr int LDC = (PHASE == 1) ? N1 : N2;
    const float* A  = (PHASE == 1) ? zin : (const float*)g_h;
    const float* Bw = (PHASE == 1) ? (const float*)g_W1p : (const float*)g_W2p;
    float* outp     = (PHASE == 1) ? (float*)g_h : outX;

    float* As = (float*)smem;
    float* Bs = (float*)(smem + 4096);

    const int m0 = blockIdx.y * 128;
    const int n0 = blockIdx.x * 128;
    const int lrow = tid >> 1;
    const int lk4  = (tid & 1) << 2;
    const float* Ap = A  + (size_t)(m0 + lrow) * K + lk4;
    const float* Bp = Bw + (size_t)(n0 + lrow) * K + lk4;
    const int tx = tid & 15;
    const int ty = tid >> 4;

    float acc[8][8];
    #pragma unroll
    for (int i = 0; i < 8; i++)
        #pragma unroll
        for (int j = 0; j < 8; j++) acc[i][j] = 0.f;

    float tr = 0.f;
    const bool do_trace = (PHASE == 2) && (blockIdx.x == 0);

    float4 av = *(const float4*)Ap;
    float4 bv = *(const float4*)Bp;

    for (int k0 = 0; k0 < K; k0 += 8) {
        As[(lk4 + 0) * 128 + lrow] = av.x;
        As[(lk4 + 1) * 128 + lrow] = av.y;
        As[(lk4 + 2) * 128 + lrow] = av.z;
        As[(lk4 + 3) * 128 + lrow] = av.w;
        Bs[(lk4 + 0) * 128 + lrow] = bv.x;
        Bs[(lk4 + 1) * 128 + lrow] = bv.y;
        Bs[(lk4 + 2) * 128 + lrow] = bv.z;
        Bs[(lk4 + 3) * 128 + lrow] = bv.w;

        if (do_trace) {
            const float4 cv = *(const float4*)(g_c + k0 + lk4);
            tr += (av.x > 0.f) ? cv.x : 0.f;
            tr += (av.y > 0.f) ? cv.y : 0.f;
            tr += (av.z > 0.f) ? cv.z : 0.f;
            tr += (av.w > 0.f) ? cv.w : 0.f;
        }
        BARF();
        if (k0 + 8 < K) {
            av = *(const float4*)(Ap + k0 + 8);
            bv = *(const float4*)(Bp + k0 + 8);
        }
        #pragma unroll
        for (int kk = 0; kk < 8; kk++) {
            float4 a0 = *(const float4*)&As[kk * 128 + ty * 4];
            float4 a1 = *(const float4*)&As[kk * 128 + ty * 4 + 64];
            float4 b0 = *(const float4*)&Bs[kk * 128 + tx * 4];
            float4 b1 = *(const float4*)&Bs[kk * 128 + tx * 4 + 64];
            float a[8] = {a0.x, a0.y, a0.z, a0.w, a1.x, a1.y, a1.z, a1.w};
            float b[8] = {b0.x, b0.y, b0.z, b0.w, b1.x, b1.y, b1.z, b1.w};
            #pragma unroll
            for (int i = 0; i < 8; i++)
                #pragma unroll
                for (int j = 0; j < 8; j++)
                    acc[i][j] += a[i] * b[j];
        }
        BARF();
    }

    const float* bias = (PHASE == 1) ? g_beff1 : g_beff2;
    const float4 be0 = *(const float4*)(bias + n0 + tx * 4);
    const float4 be1 = *(const float4*)(bias + n0 + 64 + tx * 4);
    #pragma unroll
    for (int i = 0; i < 8; i++) {
        int m = m0 + ty * 4 + (i & 3) + ((i >= 4) ? 64 : 0);
        float v[8];
        v[0] = acc[i][0] + be0.x; v[1] = acc[i][1] + be0.y;
        v[2] = acc[i][2] + be0.z; v[3] = acc[i][3] + be0.w;
        v[4] = acc[i][4] + be1.x; v[5] = acc[i][5] + be1.y;
        v[6] = acc[i][6] + be1.z; v[7] = acc[i][7] + be1.w;
        if (PHASE == 1) {
            #pragma unroll
            for (int j = 0; j < 8; j++) v[j] = fmaxf(v[j], 0.f);
        }
        float* cp = outp + (size_t)m * LDC + n0 + tx * 4;
        *(float4*)cp        = make_float4(v[0], v[1], v[2], v[3]);
        *(float4*)(cp + 64) = make_float4(v[4], v[5], v[6], v[7]);
    }
    if (do_trace) {
        float tro = __shfl_xor_sync(0xffffffffu, tr, 1);
        if ((tid & 1) == 0)
            outp[(size_t)NB * N2 + (m0 + lrow)] = -(tr + tro);
    }
}

// ---------------- mma role (warps 8-15), 64x128 tile ------------------------
template<int PHASE>
__device__ __forceinline__ void mma_role(char* smemr, float* outp,
                                         const float* __restrict__ zP,
                                         const float* __restrict__ W1P, int tidm) {
    constexpr int N    = (PHASE == 1) ? N1 : N2;
    constexpr int K    = (PHASE == 1) ? K1 : K2;
    constexpr int KS16 = K / 16;
    constexpr int NG   = N / 8;
    constexpr int NC   = K / 32;

    if (blockIdx.y >= MR / 64) return;

    const uint32_t* A1 = (PHASE == 1) ? g_zf1  : g_hf1;
    const uint32_t* A2 = (PHASE == 1) ? g_zf2  : g_hf2;
    const uint32_t* B1 = (PHASE == 1) ? g_w1f1 : g_w2f1;
    const uint32_t* B2 = (PHASE == 1) ? g_w1f2 : g_w2f2;
    const float* bias  = (PHASE == 1) ? g_beff1 : g_beff2;

    const uint32_t sbase = smem_u32(smemr);
    const int lane = tidm & 31, widm = tidm >> 5;
    const int wm = widm >> 2, wn = widm & 3;
    const int f0m = F0MG + blockIdx.y * 4;
    const int g0  = blockIdx.x * 16;

    auto load_stage = [&](int buf, int c) {
        uint32_t st = sbase + buf * ST_SZ;
        {   // A: 256 x 16B per plane
            int idx = tidm;
            int s = idx >> 7, f = (idx >> 5) & 3, tt = idx & 31;
            size_t go = (((size_t)(f0m + f) * KS16 + c * 2 + s) * 32 + tt) * 4;
            uint32_t so = (uint32_t)(((s * 4 + f) * 32 + tt) * 16);
            CP16(st + so,         A1 + go);
            CP16(st + ST_A2 + so, A2 + go);
        }
        #pragma unroll
        for (int i = 0; i < 2; i++) {      // B: 512 x 16B per plane
            int idx = tidm + i * 256;
            int s = idx >> 8, tt = (idx >> 3) & 31, q = idx & 7;
            size_t go = (((size_t)(c * 2 + s) * 32 + tt) * NG + g0 + 2 * q) * 2;
            uint32_t so = (uint32_t)((s * 32 + tt) * 144 + 16 * q);
            CP16(st + ST_B1 + so, B1 + go);
            CP16(st + ST_B2 + so, B2 + go);
        }
    };

    float acc[2][4][4];
    #pragma unroll
    for (int a = 0; a < 2; a++)
        #pragma unroll
        for (int b = 0; b < 4; b++)
            #pragma unroll
            for (int c = 0; c < 4; c++) acc[a][b][c] = 0.f;

    load_stage(0, 0); CP_COMMIT();
    load_stage(1, 1); CP_COMMIT();

    for (int c = 0; c < NC; c++) {
        CP_WAIT1();
        BARM();
        if (c + 2 < NC) load_stage((c + 2) % 3, c + 2);
        CP_COMMIT();

        uint32_t st = sbase + (c % 3) * ST_SZ;
        #pragma unroll
        for (int s = 0; s < 2; s++) {
            uint32_t a1[2][4], a2[2][4];
            #pragma unroll
            for (int mi = 0; mi < 2; mi++) {
                uint32_t ao = st + ((s * 4 + wm * 2 + mi) * 32 + lane) * 16;
                LDS128(a1[mi], ao);
                LDS128(a2[mi], ao + ST_A2);
            }
            uint32_t b1[8], b2[8];
            #pragma unroll
            for (int p = 0; p < 2; p++) {
                uint32_t bo = st + ST_B1 + (s * 32 + lane) * 144 + (wn * 4 + 2 * p) * 8;
                LDS128(&b1[4 * p], bo);
                LDS128(&b2[4 * p], bo + (ST_B2 - ST_B1));
            }
            #pragma unroll
            for (int mi = 0; mi < 2; mi++)
                #pragma unroll
                for (int ni = 0; ni < 4; ni++)
                    mma_bf16(acc[mi][ni], a1[mi], &b1[2 * ni]);
            #pragma unroll
            for (int mi = 0; mi < 2; mi++)
                #pragma unroll
                for (int ni = 0; ni < 4; ni++)
                    mma_bf16(acc[mi][ni], a1[mi], &b2[2 * ni]);
            #pragma unroll
            for (int mi = 0; mi < 2; mi++)
                #pragma unroll
                for (int ni = 0; ni < 4; ni++)
                    mma_bf16(acc[mi][ni], a2[mi], &b1[2 * ni]);
        }
    }
    CP_WAIT0();
    BARM();

    float2 bia[4];
    #pragma unroll
    for (int ni = 0; ni < 4; ni++) {
        int col = blockIdx.x * 128 + wn * 32 + ni * 8 + 2 * (lane & 3);
        bia[ni] = *(const float2*)(bias + col);
    }

    if (PHASE == 1) {
        float2 cc[4];
        #pragma unroll
        for (int ni = 0; ni < 4; ni++) {
            int col = blockIdx.x * 128 + wn * 32 + ni * 8 + 2 * (lane & 3);
            cc[ni] = *(const float2*)(g_c + col);
        }
        float* S   = (float*)smemr;                 // [128 n][64 m] stride 68
        float* TRB = (float*)(smemr + 34816);       // [4 wn][64 rows]
        const int rb = MF + blockIdx.y * 64;
        float tr[4] = {0, 0, 0, 0};
        #pragma unroll
        for (int mi = 0; mi < 2; mi++)
            #pragma unroll
            for (int ni = 0; ni < 4; ni++)
                #pragma unroll
                for (int h2 = 0; h2 < 2; h2++) {
                    int mloc = wm * 32 + mi * 16 + (lane >> 2) + 8 * h2;
                    int nb = wn * 32 + ni * 8 + 2 * (lane & 3);
                    float v0 = acc[mi][ni][2 * h2 + 0] + bia[ni].x;
                    float v1 = acc[mi][ni][2 * h2 + 1] + bia[ni].y;
                    bool m0k = (fabsf(v0) > TAU) ? (v0 > 0.f)
                        : exact_mask(zP, W1P, rb + mloc, blockIdx.x * 128 + nb);
                    bool m1k = (fabsf(v1) > TAU) ? (v1 > 0.f)
                        : exact_mask(zP, W1P, rb + mloc, blockIdx.x * 128 + nb + 1);
                    if (m0k) tr[mi * 2 + h2] += cc[ni].x;
                    if (m1k) tr[mi * 2 + h2] += cc[ni].y;
                    S[nb * 68 + mloc]       = fmaxf(v0, 0.f);
                    S[(nb + 1) * 68 + mloc] = fmaxf(v1, 0.f);
                }
        #pragma unroll
        for (int r = 0; r < 4; r++) {
            tr[r] += __shfl_xor_sync(0xffffffffu, tr[r], 1);
            tr[r] += __shfl_xor_sync(0xffffffffu, tr[r], 2);
        }
        if ((lane & 3) == 0) {
            #pragma unroll
            for (int r = 0; r < 4; r++) {
                int row = wm * 32 + (r >> 1) * 16 + (r & 1) * 8 + (lane >> 2);
                TRB[wn * 64 + row] = tr[r];
            }
        }
        BARM();
        // h -> bf16 A-frag planes for phase 2 (4096 words)
        #pragma unroll
        for (int i = 0; i < 16; i++) {
            int idx = tidm + i * 256;
            int fl = idx >> 10, sl = (idx >> 7) & 7, tt = (idx >> 2) & 31, jr = idx & 3;
            int mloc = fl * 16 + (tt >> 2) + 8 * (jr & 1);
            int qloc = sl * 8 + (tt & 3) + 4 * (jr >> 1);
            float v0 = S[(2 * qloc) * 68 + mloc];
            float v1 = S[(2 * qloc + 1) * 68 + mloc];
            uint32_t w1, w2;
            split2(v0, v1, w1, w2);
            size_t go = (((size_t)(f0m + fl) * (K2 / 16) + blockIdx.x * 8 + sl) * 32 + tt) * 4 + jr;
            g_hf1[go] = w1;
            g_hf2[go] = w2;
        }
        if (tidm < 64) {
            float s4 = TRB[tidm] + TRB[64 + tidm] + TRB[128 + tidm] + TRB[192 + tidm];
            g_trp[blockIdx.x][rb + tidm] = s4;
        }
    } else {
        #pragma unroll
        for (int mi = 0; mi < 2; mi++)
            #pragma unroll
            for (int ni = 0; ni < 4; ni++)
                #pragma unroll
                for (int h2 = 0; h2 < 2; h2++) {
                    int m = MF + blockIdx.y * 64 + wm * 32 + mi * 16 + (lane >> 2) + 8 * h2;
                    int n = blockIdx.x * 128 + wn * 32 + ni * 8 + 2 * (lane & 3);
                    float2 o;
                    o.x = acc[mi][ni][2 * h2 + 0] + bia[ni].x;
                    o.y = acc[mi][ni][2 * h2 + 1] + bia[ni].y;
                    *(float2*)(outp + (size_t)m * N2 + n) = o;
                }
    }
}

// ---------------- hybrid kernel --------------------------------------------
template<int PHASE>
__global__ void __launch_bounds__(512, 1)
hybrid(float* __restrict__ outp, const float* __restrict__ zP,
       const float* __restrict__ W1P) {
    extern __shared__ char smem[];
    int tid = threadIdx.x;
    if (tid < 256) {
        ffma_role<PHASE>(smem, outp, zP, tid);
    } else {
        mma_role<PHASE>(smem + MM_OFF, outp, zP, W1P, tid - 256);
    }
}

// ---------------------------------------------------------------------------
extern "C" void kernel_launch(void* const* d_in, const int* in_sizes, int n_in,
                              void* d_out, int out_size) {
    const float* t  = (const float*)d_in[0];
    const float* z  = (const float*)d_in[1];
    const float* W1 = (const float*)d_in[3];
    const float* b1 = (const float*)d_in[4];
    const float* W2 = (const float*)d_in[5];
    const float* b2 = (const float*)d_in[6];
    float* out = (float*)d_out;     // dz (NB*512) then dlogp (NB)

    cudaFuncSetAttribute(hybrid<1>, cudaFuncAttributeMaxDynamicSharedMemorySize, SMEM_BYTES);
    cudaFuncSetAttribute(hybrid<2>, cudaFuncAttributeMaxDynamicSharedMemorySize, SMEM_BYTES);

    prep_pack<<<(N1 * K1 + N2 * K2 + 255) / 256, 256>>>(W1, W2);
    prep_w<<<(N1 * K1 / 2 + N2 * K2 / 2 + 255) / 256, 256>>>(W1, W2);
    prep_zf<<<(MR * K1 / 4) / 256, 256>>>(z);
    prep_cbias<<<8, 128>>>(t, W1, b1, W2, b2);

    { dim3 g(N1 / 128, MF / 128); hybrid<1><<<g, 512, SMEM_BYTES>>>(nullptr, z, W1); }
    { dim3 g(N2 / 128, MF / 128); hybrid<2><<<g, 512, SMEM_BYTES>>>(out, z, W1); }

    trace_combine<<<MR / 256, 256>>>(out);
}